// round 1
// baseline (speedup 1.0000x reference)
#include <cuda_runtime.h>
#include <math.h>

// ----------------------------------------------------------------------------
// qMT SPGR steady-state signal, 1M voxels.
//   Pipeline (all graph-capturable, no allocations):
//     k0: reset scratch (min/max bits)
//     k1: grid-stride min/max reduction of T2_m  -> __device__ globals
//     k2: build 4096-entry G(T2_m) super-Lorentzian table (100-pt trapezoid)
//     k3: per-voxel closed-form 2x2 Bloch-McConnell steady state w/ table lerp
// ----------------------------------------------------------------------------

#define NTAB 4096
#define NINT 100
#define PI_F 3.14159265358979f

__device__ float g_tab[NTAB];
__device__ int   g_min_bits;
__device__ int   g_max_bits;

__global__ void reset_kernel() {
    g_min_bits = 0x7F800000;   // +inf
    g_max_bits = 0;            // 0.0f  (T2_m > 0 always)
}

// Min/max of positive floats: int-bit ordering matches float ordering.
__global__ void minmax_kernel(const float* __restrict__ t2m, int n) {
    int i = blockIdx.x * blockDim.x + threadIdx.x;
    int stride = gridDim.x * blockDim.x;
    float lo = __int_as_float(0x7F800000);
    float hi = 0.0f;
    for (; i < n; i += stride) {
        float v = t2m[i];
        lo = fminf(lo, v);
        hi = fmaxf(hi, v);
    }
#pragma unroll
    for (int o = 16; o > 0; o >>= 1) {
        lo = fminf(lo, __shfl_xor_sync(0xFFFFFFFFu, lo, o));
        hi = fmaxf(hi, __shfl_xor_sync(0xFFFFFFFFu, hi, o));
    }
    if ((threadIdx.x & 31) == 0) {
        atomicMin(&g_min_bits, __float_as_int(lo));
        atomicMax(&g_max_bits, __float_as_int(hi));
    }
}

// G(delta, T2r): 100-point trapezoid over theta in [0, pi/2], matching the
// reference formula. Full-precision expf here (only 4096*100 evals).
__global__ void table_kernel(const float* __restrict__ mt_offset_p) {
    int i = blockIdx.x * blockDim.x + threadIdx.x;
    if (i >= NTAB) return;
    float tmin = __int_as_float(g_min_bits);
    float tmax = __int_as_float(g_max_bits);
    float dt   = (tmax - tmin) * (1.0f / (float)(NTAB - 1));
    float x    = tmin + dt * (float)i;          // T2_m sample
    float delta = *mt_offset_p;

    const float h = (PI_F * 0.5f) / (float)(NINT - 1);
    const float c_sqrt2opi = 0.7978845608028654f;   // sqrt(2/pi)
    float sum = 0.0f;
    for (int j = 0; j < NINT; j++) {
        float th = h * (float)j;
        float ct = cosf(th);
        float st = sinf(th);
        float term = fabsf(3.0f * ct * ct - 1.0f);
        term = fmaxf(term, 1e-6f);
        float t2e = x / term;
        float w   = 2.0f * PI_F * delta * t2e;
        float val = c_sqrt2opi * t2e * expf(-2.0f * w * w);
        float fj  = val * st;
        if (j == 0 || j == NINT - 1) fj *= 0.5f;
        sum += fj;
    }
    g_tab[i] = sum * h;
}

__global__ void __launch_bounds__(256) voxel_kernel(
    const float* __restrict__ f_in,
    const float* __restrict__ kmf_in,
    const float* __restrict__ r1f_in,
    const float* __restrict__ r1m_in,
    const float* __restrict__ t2m_in,
    const float* __restrict__ tr_p,
    const float* __restrict__ exc_p,
    const float* __restrict__ mtfa_p,
    const float* __restrict__ mtdur_p,
    float* __restrict__ out,
    int n)
{
    __shared__ float stab[NTAB];   // 16 KB: G lookup table in shared
    for (int j = threadIdx.x; j < NTAB; j += blockDim.x)
        stab[j] = g_tab[j];
    __syncthreads();

    int i = blockIdx.x * blockDim.x + threadIdx.x;
    if (i >= n) return;

    // Uniform scalars (broadcast LDG, L1 hits)
    const float tr     = *tr_p;
    const float exc    = (*exc_p) * (PI_F / 180.0f);
    const float mt_rad = (*mtfa_p) * (PI_F / 180.0f);
    const float mt_dur = *mtdur_p;
    const float w1     = mt_rad / mt_dur;
    const float Wc     = PI_F * (w1 * w1) * (mt_dur / tr);   // W = Wc * g

    const float tmin  = __int_as_float(g_min_bits);
    const float tmax  = __int_as_float(g_max_bits);
    const float range = tmax - tmin;
    const float inv_dt = (range > 0.0f) ? ((float)(NTAB - 1) / range) : 0.0f;

    // Per-voxel inputs
    const float f   = f_in[i];
    const float kmf = kmf_in[i];
    const float R1f = r1f_in[i];
    const float R1m = r1m_in[i];
    const float t2m = t2m_in[i];

    // --- G table lerp ---
    float pos = (t2m - tmin) * inv_dt;
    pos = fminf(fmaxf(pos, 0.0f), (float)(NTAB - 1));
    int idx = (int)pos;
    if (idx > NTAB - 2) idx = NTAB - 2;
    float fr = pos - (float)idx;
    float g0 = stab[idx];
    float g1 = stab[idx + 1];
    float g  = fmaf(fr, g1 - g0, g0);

    // --- 2x2 Bloch-McConnell ---
    const float W   = Wc * g;
    const float kfr = kmf * f * __frcp_rn(1.0f - f + 1e-9f);

    const float a = -(R1f + kfr);
    const float b = kmf;
    const float c = kfr;
    const float d = -(R1m + kmf + W);

    // E = expm(A*tr) closed form: eigenvalues m +/- s (s real, bounded away
    // from 0 since b*c = kmf*kfr > 0 and |p| adds).
    const float at = a * tr, bt = b * tr, ct = c * tr, dtt = d * tr;
    const float m = 0.5f * (at + dtt);
    const float p = 0.5f * (at - dtt);
    const float s = sqrtf(fmaf(p, p, bt * ct));
    const float e1 = __expf(m + s);
    const float e2 = __expf(m - s);
    const float u  = (e1 - e2) * __frcp_rn(2.0f * s);   // e^m sinh(s)/s
    const float v  = 0.5f * (e1 + e2);                  // e^m cosh(s)
    const float E11 = fmaf(u, p, v);
    const float E12 = u * bt;
    const float E21 = u * ct;
    const float E22 = fmaf(-u, p, v);

    // M* = -A^{-1} B  (fixed point);  M_relax = (I - E) M*
    const float B0 = R1f * (1.0f - f);
    const float B1 = R1m * f;
    const float det    = fmaf(a, d, -b * c);            // > 0
    const float invdet = __frcp_rn(det);
    const float Ms0 = -(d * B0 - b * B1) * invdet;
    const float Ms1 = -(a * B1 - c * B0) * invdet;
    const float r0 = (1.0f - E11) * Ms0 - E12 * Ms1;
    const float r1 = (1.0f - E22) * Ms1 - E21 * Ms0;

    // Solve (I - E Q) x = M_relax, Q = diag(cos(exc), 1)
    const float ce = cosf(exc);
    const float se = sinf(exc);
    const float M00 = 1.0f - E11 * ce;
    const float M01 = -E12;
    const float M10 = -E21 * ce;
    const float M11 = 1.0f - E22;
    const float dM  = fmaf(M00, M11, -M01 * M10);
    const float x0  = (M11 * r0 - M01 * r1) * __frcp_rn(dM);

    out[i] = x0 * se;
}

extern "C" void kernel_launch(void* const* d_in, const int* in_sizes, int n_in,
                              void* d_out, int out_size) {
    // metadata order: f, k_mf, R1_f, R1_m, T2_f, T2_m, tr, exc_fa, mt_fa,
    //                 mt_offset, mt_dur
    const float* f_in    = (const float*)d_in[0];
    const float* kmf_in  = (const float*)d_in[1];
    const float* r1f_in  = (const float*)d_in[2];
    const float* r1m_in  = (const float*)d_in[3];
    // d_in[4] = T2_f (unused by the model)
    const float* t2m_in  = (const float*)d_in[5];
    const float* tr_p    = (const float*)d_in[6];
    const float* exc_p   = (const float*)d_in[7];
    const float* mtfa_p  = (const float*)d_in[8];
    const float* mtoff_p = (const float*)d_in[9];
    const float* mtdur_p = (const float*)d_in[10];
    float* out = (float*)d_out;
    const int n = in_sizes[5];   // voxel count (T2_m length)

    reset_kernel<<<1, 1>>>();
    minmax_kernel<<<256, 256>>>(t2m_in, n);
    table_kernel<<<NTAB / 256, 256>>>(mtoff_p);
    voxel_kernel<<<(n + 255) / 256, 256>>>(f_in, kmf_in, r1f_in, r1m_in,
                                           t2m_in, tr_p, exc_p, mtfa_p,
                                           mtdur_p, out, n);
}

// round 5
// speedup vs baseline: 2.7350x; 2.7350x over previous
#include <cuda_runtime.h>
#include <math.h>

// ----------------------------------------------------------------------------
// qMT SPGR steady-state signal, 1M voxels. Two launches only:
//   k1 (table): 8192-entry G(T2_m) super-Lorentzian table over a FIXED
//       bit-space domain [1e-9, 1e-3] (float-bit-linear ~ log spacing, so no
//       data-dependent min/max pass is needed), + uniform scalar precompute.
//   k2 (voxel): 4 voxels/thread, float4 I/O, closed-form 2x2 Bloch-McConnell
//       steady state with an L1-resident table lerp.
// ----------------------------------------------------------------------------

#define NTAB 8192
#define NINT 100
#define PI_F 3.14159265358979f

// Fixed table domain in float-bit space.
#define XLO 1e-9f
#define XHI 1e-3f

__device__ float  g_tab[NTAB];
__device__ float4 g_scal;     // {tr, Wc, cos(exc), sin(exc)}

// ---------------------------------------------------------------------------
// Table kernel: g_tab[i] = G(delta, x_i) with x_i = as_float(B0 + i*STEP).
// The 100 theta-dependent factors are shared across all table entries, so
// precompute them once into smem; inner loop is then 1 EX2 + 2 FMA per point.
// ---------------------------------------------------------------------------
__global__ void __launch_bounds__(128) table_kernel(
    const float* __restrict__ tr_p,
    const float* __restrict__ exc_p,
    const float* __restrict__ mtfa_p,
    const float* __restrict__ mtoff_p,
    const float* __restrict__ mtdur_p)
{
    __shared__ float sw[NINT];   // sqrt(2/pi)*sin(th)*trap*h / term
    __shared__ float sc[NINT];   // 2*(2*pi*delta/term)^2

    const float delta = *mtoff_p;
    const int t = threadIdx.x;
    if (t < NINT) {
        const float h = (PI_F * 0.5f) / (float)(NINT - 1);
        float th = h * (float)t;
        float st = sinf(th);
        float ctt = cosf(th);
        float term = fabsf(fmaf(3.0f * ctt, ctt, -1.0f));
        term = fmaxf(term, 1e-6f);
        float trap = (t == 0 || t == NINT - 1) ? 0.5f : 1.0f;
        float invterm = 1.0f / term;
        sw[t] = 0.7978845608028654f * st * trap * h * invterm;
        float q = 2.0f * PI_F * delta * invterm;
        sc[t] = 2.0f * q * q;
    }
    __syncthreads();

    const int i = blockIdx.x * blockDim.x + t;
    const int B0 = __float_as_int(XLO);
    const int B1 = __float_as_int(XHI);
    const int STEP = (B1 - B0) / (NTAB - 1);
    if (i < NTAB) {
        float x  = __int_as_float(B0 + i * STEP);
        float x2 = x * x;
        float sum = 0.0f;
#pragma unroll 4
        for (int j = 0; j < NINT; j++)
            sum += sw[j] * __expf(-sc[j] * x2);
        g_tab[i] = x * sum;
    }

    // One thread computes the uniform scalars for the voxel kernel.
    if (i == 0) {
        float tr     = *tr_p;
        float exc    = (*exc_p) * (PI_F / 180.0f);
        float mt_rad = (*mtfa_p) * (PI_F / 180.0f);
        float mt_dur = *mtdur_p;
        float w1     = mt_rad / mt_dur;
        float Wc     = PI_F * (w1 * w1) * (mt_dur / tr);
        g_scal = make_float4(tr, Wc, cosf(exc), sinf(exc));
    }
}

// ---------------------------------------------------------------------------
// Per-voxel closed-form 2x2 Bloch-McConnell steady state.
// ---------------------------------------------------------------------------
__device__ __forceinline__ float voxel_compute(
    float f, float kmf, float R1f, float R1m, float t2m,
    float tr, float Wc, float ce, float se,
    int B0, float inv_step)
{
    // --- G table lerp in float-bit space ---
    float pos = (float)(__float_as_int(t2m) - B0) * inv_step;
    pos = fminf(fmaxf(pos, 0.0f), (float)(NTAB - 1) - 0.001f);
    int idx = (int)pos;
    float fr = pos - (float)idx;
    float g0 = __ldg(&g_tab[idx]);
    float g1 = __ldg(&g_tab[idx + 1]);
    float g  = fmaf(fr, g1 - g0, g0);

    // --- 2x2 Bloch-McConnell ---
    const float W   = Wc * g;
    const float kfr = kmf * f * __frcp_rn(1.0f - f + 1e-9f);

    const float a = -(R1f + kfr);
    const float b = kmf;
    const float c = kfr;
    const float d = -(R1m + kmf + W);

    // E = expm(A*tr), closed form via eigenvalues m +/- s (s real & bounded
    // away from 0 since b*c > 0).
    const float at = a * tr, bt = b * tr, ct = c * tr, dtt = d * tr;
    const float m = 0.5f * (at + dtt);
    const float p = 0.5f * (at - dtt);
    const float s = sqrtf(fmaf(p, p, bt * ct));
    const float e1 = __expf(m + s);
    const float e2 = __expf(m - s);
    const float u  = (e1 - e2) * __frcp_rn(2.0f * s);   // e^m sinh(s)/s
    const float v  = 0.5f * (e1 + e2);                  // e^m cosh(s)
    const float E11 = fmaf(u, p, v);
    const float E12 = u * bt;
    const float E21 = u * ct;
    const float E22 = fmaf(-u, p, v);

    // M* = -A^{-1} B;  M_relax = (I - E) M*
    const float B0v = R1f * (1.0f - f);
    const float B1v = R1m * f;
    const float det    = fmaf(a, d, -b * c);
    const float invdet = __frcp_rn(det);
    const float Ms0 = -(d * B0v - b * B1v) * invdet;
    const float Ms1 = -(a * B1v - c * B0v) * invdet;
    const float r0 = (1.0f - E11) * Ms0 - E12 * Ms1;
    const float r1 = (1.0f - E22) * Ms1 - E21 * Ms0;

    // Solve (I - E Q) x = M_relax, Q = diag(cos(exc), 1)
    const float M00 = 1.0f - E11 * ce;
    const float M01 = -E12;
    const float M10 = -E21 * ce;
    const float M11 = 1.0f - E22;
    const float dM  = fmaf(M00, M11, -M01 * M10);
    const float x0  = (M11 * r0 - M01 * r1) * __frcp_rn(dM);

    return x0 * se;
}

__global__ void __launch_bounds__(256) voxel_kernel(
    const float* __restrict__ f_in,
    const float* __restrict__ kmf_in,
    const float* __restrict__ r1f_in,
    const float* __restrict__ r1m_in,
    const float* __restrict__ t2m_in,
    float* __restrict__ out,
    int n)
{
    const float4 sc = g_scal;
    const float tr = sc.x, Wc = sc.y, ce = sc.z, se = sc.w;

    const int B0 = __float_as_int(XLO);
    const int B1 = __float_as_int(XHI);
    const int STEP = (B1 - B0) / (NTAB - 1);
    const float inv_step = 1.0f / (float)STEP;

    const int base = (blockIdx.x * blockDim.x + threadIdx.x) * 4;
    if (base >= n) return;

    if (base + 3 < n) {
        const float4 vf  = *(const float4*)(f_in   + base);
        const float4 vk  = *(const float4*)(kmf_in + base);
        const float4 va  = *(const float4*)(r1f_in + base);
        const float4 vb  = *(const float4*)(r1m_in + base);
        const float4 vt  = *(const float4*)(t2m_in + base);
        float4 r;
        r.x = voxel_compute(vf.x, vk.x, va.x, vb.x, vt.x, tr, Wc, ce, se, B0, inv_step);
        r.y = voxel_compute(vf.y, vk.y, va.y, vb.y, vt.y, tr, Wc, ce, se, B0, inv_step);
        r.z = voxel_compute(vf.z, vk.z, va.z, vb.z, vt.z, tr, Wc, ce, se, B0, inv_step);
        r.w = voxel_compute(vf.w, vk.w, va.w, vb.w, vt.w, tr, Wc, ce, se, B0, inv_step);
        *(float4*)(out + base) = r;
    } else {
        for (int i = base; i < n; i++) {
            out[i] = voxel_compute(f_in[i], kmf_in[i], r1f_in[i], r1m_in[i],
                                   t2m_in[i], tr, Wc, ce, se, B0, inv_step);
        }
    }
}

extern "C" void kernel_launch(void* const* d_in, const int* in_sizes, int n_in,
                              void* d_out, int out_size) {
    // metadata order: f, k_mf, R1_f, R1_m, T2_f, T2_m, tr, exc_fa, mt_fa,
    //                 mt_offset, mt_dur
    const float* f_in    = (const float*)d_in[0];
    const float* kmf_in  = (const float*)d_in[1];
    const float* r1f_in  = (const float*)d_in[2];
    const float* r1m_in  = (const float*)d_in[3];
    const float* t2m_in  = (const float*)d_in[5];
    const float* tr_p    = (const float*)d_in[6];
    const float* exc_p   = (const float*)d_in[7];
    const float* mtfa_p  = (const float*)d_in[8];
    const float* mtoff_p = (const float*)d_in[9];
    const float* mtdur_p = (const float*)d_in[10];
    float* out = (float*)d_out;
    const int n = in_sizes[5];

    table_kernel<<<NTAB / 128, 128>>>(tr_p, exc_p, mtfa_p, mtoff_p, mtdur_p);

    const int threads = (n + 3) / 4;
    voxel_kernel<<<(threads + 255) / 256, 256>>>(f_in, kmf_in, r1f_in, r1m_in,
                                                 t2m_in, out, n);
}